// round 13
// baseline (speedup 1.0000x reference)
#include <cuda_runtime.h>
#include <cuda_bf16.h>
#include <cstdint>

#define N_ROIS   32768
#define N_GT     1024
#define N_IMAGES 8
#define NT       512
#define NB       296                 // 2 blocks per SM, single wave
#define NKEY     64                  // batch(3b) x area-octave(3b)
#define NGT_PAD  1216                // 1024 + 64*3 max pads

// oct = clamp(exp2(area) - 8, 0, 7); areas in [289, 66049] -> biased exp 135..143
__device__ __forceinline__ int area_oct(float a) {
    int e = (__float_as_int(a) >> 23) & 255;
    return min(max(e - 135, 0), 7);
}

// approx-rcp IoU argmax step; union via FFMA (no area array)
#define IOU_STEP(J, BB, BJ) {                                   \
    float4 g  = sbox[J];                                        \
    float iw  = fminf(rx2p, g.z) - fmaxf(rx1, g.x);             \
    float ih  = fminf(ry2p, g.w) - fmaxf(ry1, g.y);             \
    float inter = fmaxf(iw, 0.0f) * ih;                         \
    float uni = fmaf(g.z - g.x, g.w - g.y, area_r - inter);     \
    float iouv = __fdividef(inter, uni);                        \
    bool better = iouv > (BB);                                  \
    BB = better ? iouv : (BB);                                  \
    BJ = better ? (J)  : (BJ);                                  \
}

#define MERGE(OB, OJ) {                                         \
    bool take = ((OB) > best) ||                                \
        ((OB) == best && (unsigned)(OJ) < (unsigned)bj);        \
    best = take ? (OB) : best;                                  \
    bj   = take ? (OJ) : bj;                                    \
}

__global__ void __launch_bounds__(NT, 2) roitarget_fused(const float* __restrict__ rois,
                                                         const int* __restrict__ rb,
                                                         const float* __restrict__ gt,
                                                         const int* __restrict__ gb,
                                                         float* __restrict__ out) {
    __shared__ float  sgt[5 * N_GT];       // 20KB raw staged gt (coalesced)
    __shared__ float4 sbox[NGT_PAD];       // 19.5KB compacted x1,y1,x2+1,y2+1 (+pads)
    __shared__ float  slab[NGT_PAD];       // 4.9KB labels
    __shared__ float4 sroi[128];           // 2KB ROI coords by local index
    __shared__ int    scnt_i[1056];        // u16 [64 keys][33]: GT counts -> excl
    __shared__ int    rcnt_i[160];         // u16 [64 keys][5]: ROI counts -> excl
    __shared__ int    stot[NKEY];          // GT bucket totals
    __shared__ int    rtot[NKEY];          // ROI bucket totals
    __shared__ int    soff64[NKEY + 1];    // padded GT bucket offsets
    __shared__ int    rboff[NKEY + 1];     // ROI bucket offsets (unpadded)
    __shared__ int    sprovk[128], sprovr[128];
    __shared__ int    ssrc[128];           // grouped pos -> local ROI index
    __shared__ int    ssk[128];            // grouped pos -> key

    unsigned short* scnt16 = (unsigned short*)scnt_i;   // [k*33 + chunk]
    unsigned short* rcnt16 = (unsigned short*)rcnt_i;   // [k*5  + chunk]

    const int tid  = threadIdx.x;
    const int w    = tid >> 5;
    const int lane = tid & 31;
    const unsigned lt = (1u << lane) - 1u;

    const int start = (blockIdx.x * N_ROIS) / NB;
    const int next  = ((blockIdx.x + 1) * N_ROIS) / NB;
    const int nroi  = next - start;        // 110 or 111

    // ---------- A: coalesced staging, zero counts, ROI loads ----------
#pragma unroll
    for (int k = 0; k < 10; k++) sgt[tid + k * NT] = gt[tid + k * NT];
    const int ba  = gb[tid];
    const int bb2 = gb[tid + NT];
#pragma unroll
    for (int k = 0; k < 3; k++) { int idx = tid + k * NT; if (idx < 1056) scnt_i[idx] = 0; }
    if (tid < 160) rcnt_i[tid] = 0;

    int keyr = 999;
    if (tid < nroi) {
        const int i = start + tid;
        float4 rv = make_float4(rois[5*i+0], rois[5*i+1], rois[5*i+2], rois[5*i+3]);
        sroi[tid] = rv;
        float arr = ((rv.z - rv.x) + 1.0f) * ((rv.w - rv.y) + 1.0f);
        keyr = rb[i] * 8 + area_oct(arr);
    }
    __syncthreads();                       // sync 1

    // ---------- B: parse own GTs, keys, match_any counting ----------
    const float ax1 = sgt[5*tid+0], ay1 = sgt[5*tid+1];
    const float ax2 = sgt[5*tid+2], ay2 = sgt[5*tid+3], acl = sgt[5*tid+4];
    const float aga = ((ax2 - ax1) + 1.0f) * ((ay2 - ay1) + 1.0f);
    const int keya = ba * 8 + area_oct(aga);
    unsigned ma = __match_any_sync(0xffffffffu, keya);
    const int ranka = __popc(ma & lt);
    if (!(ma & lt)) scnt16[keya * 33 + w] = (unsigned short)__popc(ma);

    const int jb = tid + NT;
    const float bx1 = sgt[5*jb+0], by1 = sgt[5*jb+1];
    const float bx2 = sgt[5*jb+2], by2 = sgt[5*jb+3], bcl = sgt[5*jb+4];
    const float agb = ((bx2 - bx1) + 1.0f) * ((by2 - by1) + 1.0f);
    const int keyb = bb2 * 8 + area_oct(agb);
    unsigned mb = __match_any_sync(0xffffffffu, keyb);
    const int rankb = __popc(mb & lt);
    if (!(mb & lt)) scnt16[keyb * 33 + 16 + w] = (unsigned short)__popc(mb);

    if (w < 4) {                           // ROI grouping (keyr=999 for invalid lanes)
        unsigned mr = __match_any_sync(0xffffffffu, keyr);
        int rankr = __popc(mr & lt);
        if (keyr < NKEY && !(mr & lt)) rcnt16[keyr * 5 + w] = (unsigned short)__popc(mr);
        sprovk[tid] = keyr;
        sprovr[tid] = rankr;
    }
    __syncthreads();                       // sync 2

    // ---------- C: scans (16 warps x 4 GT buckets; threads<64: ROI serial) ----------
#pragma unroll
    for (int i = 0; i < 4; i++) {
        int k = w * 4 + i;
        int v = (int)scnt16[k * 33 + lane];
        int s = v;
#pragma unroll
        for (int d = 1; d < 32; d <<= 1) {
            int t = __shfl_up_sync(0xffffffffu, s, d);
            if (lane >= d) s += t;
        }
        scnt16[k * 33 + lane] = (unsigned short)(s - v);
        if (lane == 31) stot[k] = s;
    }
    if (tid < NKEY) {
        int run = 0;
#pragma unroll
        for (int c = 0; c < 4; c++) {
            int v = (int)rcnt16[tid * 5 + c];
            rcnt16[tid * 5 + c] = (unsigned short)run;
            run += v;
        }
        rtot[tid] = run;
    }
    __syncthreads();                       // sync 3

    // ---------- D: bucket offsets (warp-redundant, identical values) ----------
    {
        int t0 = stot[lane], t1 = stot[lane + 32];
        int p0 = (t0 + 3) & ~3, p1 = (t1 + 3) & ~3;
        int s0 = p0, s1 = p1;
#pragma unroll
        for (int d = 1; d < 32; d <<= 1) {
            int u = __shfl_up_sync(0xffffffffu, s0, d); if (lane >= d) s0 += u;
            int v = __shfl_up_sync(0xffffffffu, s1, d); if (lane >= d) s1 += v;
        }
        int tot0 = __shfl_sync(0xffffffffu, s0, 31);
        soff64[lane]      = s0 - p0;
        soff64[lane + 32] = tot0 + s1 - p1;
        if (lane == 31) soff64[64] = tot0 + s1;

        int u0 = rtot[lane], u1 = rtot[lane + 32];
        int r0 = u0, r1 = u1;
#pragma unroll
        for (int d = 1; d < 32; d <<= 1) {
            int u = __shfl_up_sync(0xffffffffu, r0, d); if (lane >= d) r0 += u;
            int v = __shfl_up_sync(0xffffffffu, r1, d); if (lane >= d) r1 += v;
        }
        int rt0 = __shfl_sync(0xffffffffu, r0, 31);
        rboff[lane]      = r0 - u0;
        rboff[lane + 32] = rt0 + r1 - u1;
        if (lane == 31) rboff[64] = rt0 + r1;
    }
    __syncwarp();

    // ---------- E: scatter GTs, pads, ROIs ----------
    {
        int da = soff64[keya] + (int)scnt16[keya * 33 + w] + ranka;
        sbox[da] = make_float4(ax1, ay1, ax2 + 1.0f, ay2 + 1.0f);
        slab[da] = acl;
        int db = soff64[keyb] + (int)scnt16[keyb * 33 + 16 + w] + rankb;
        sbox[db] = make_float4(bx1, by1, bx2 + 1.0f, by2 + 1.0f);
        slab[db] = bcl;
    }
    if (tid < 192) {                        // pads: never win (inter=0, uni>0)
        int k = tid / 3, p = tid % 3;
        int cnt = stot[k];
        if (p < ((cnt + 3) & ~3) - cnt) {
            int slot = soff64[k] + cnt + p;
            sbox[slot] = make_float4(3e9f, 0.0f, 3.5e9f, 1e9f);
            slab[slot] = 0.0f;
        }
    }
    if (tid < nroi) {
        int kk = sprovk[tid];
        int dest = rboff[kk] + (int)rcnt16[kk * 5 + (tid >> 5)] + sprovr[tid];
        ssrc[dest] = tid;
        ssk[dest]  = kk;
    }
    __syncthreads();                       // sync 4

    // ---------- F: 4 threads per ROI over the 3-octave window ----------
    const int s = tid >> 2;                // ROI slot 0..127
    const int q = tid & 3;                 // quarter
    const bool valid = (s < nroi);
    const int loc = valid ? ssrc[s] : 0;
    const int key = valid ? ssk[s]  : 0;

    const float4 rr = sroi[loc];
    const float rx1 = rr.x, ry1 = rr.y;
    const float rx2p = rr.z + 1.0f;
    const float ry2p = rr.w + 1.0f;
    const float ew = (rr.z - rx1) + 1.0f;
    const float eh = (rr.w - ry1) + 1.0f;
    const float area_r = ew * eh;

    const int oc  = key & 7;
    const int klo = key - (oc > 0 ? 1 : 0);
    const int khi = key + (oc < 7 ? 1 : 0);
    const int js  = soff64[klo];
    const int je  = soff64[khi + 1];
    const int n4  = valid ? ((je - js) >> 2) : 0;

    float bb0 = 0.0f; int bj0 = -1;
    float bb1 = 0.0f; int bj1 = -1;

    int j = js + q;
    int t = 0;
    for (; t + 2 <= n4; t += 2, j += 8) {
        IOU_STEP(j,     bb0, bj0);
        IOU_STEP(j + 4, bb1, bj1);
    }
    if (t < n4) { IOU_STEP(j, bb0, bj0); }

    float best = bb0; int bj = bj0;
    MERGE(bb1, bj1);
#pragma unroll
    for (int d = 1; d <= 2; d <<= 1) {
        float ob = __shfl_xor_sync(0xffffffffu, best, d);
        int   oj = __shfl_xor_sync(0xffffffffu, bj, d);
        MERGE(ob, oj);
    }

    if (q == 0 && valid) {
        const bool fg = (bj >= 0) && (best >= 0.5f);
        const int ii = start + loc;

        float lbl = 0.0f, dx = 0.0f, dy = 0.0f, dw = 0.0f, dh = 0.0f, wgt = 0.0f;
        if (fg) {
            float4 g = sbox[bj];
            float gw  = g.z - g.x;             // (x2+1) - x1
            float gh  = g.w - g.y;
            float gcx = g.x + 0.5f * gw;
            float gcy = g.y + 0.5f * gh;
            float ecx = rx1 + 0.5f * ew;
            float ecy = ry1 + 0.5f * eh;
            dx = __fdividef(gcx - ecx, ew);
            dy = __fdividef(gcy - ecy, eh);
            dw = __logf(__fdividef(gw, ew));
            dh = __logf(__fdividef(gh, eh));
            lbl = slab[bj];
            wgt = 1.0f;
        }

        // Layout: labels[N] | deltas[N][4] | bbwgts[N][1]
        out[ii] = lbl;
        reinterpret_cast<float4*>(out + N_ROIS)[ii] = make_float4(dx, dy, dw, dh);
        out[N_ROIS * 5 + ii] = wgt;
    }
}

extern "C" void kernel_launch(void* const* d_in, const int* in_sizes, int n_in,
                              void* d_out, int out_size) {
    const float* rois = (const float*)d_in[0];
    const int*   rb   = (const int*)d_in[1];
    const float* gt   = (const float*)d_in[2];
    const int*   gb   = (const int*)d_in[3];
    float* out = (float*)d_out;

    roitarget_fused<<<NB, NT>>>(rois, rb, gt, gb, out);
}

// round 14
// speedup vs baseline: 1.0226x; 1.0226x over previous
#include <cuda_runtime.h>
#include <cuda_bf16.h>
#include <cstdint>

#define N_ROIS   32768
#define N_GT     1024
#define N_IMAGES 8
#define NT       512
#define NB       296                 // 2 blocks per SM, single wave
#define NGT_PAD  1152

// approx-rcp IoU argmax step (comparisons only); ag from sarea
#define IOU_STEP(J, BB, BJ) {                                   \
    float4 g  = sbox[J];                                        \
    float ag  = sarea[J];                                       \
    float iw  = fminf(rx2p, g.z) - fmaxf(rx1, g.x);             \
    float ih  = fminf(ry2p, g.w) - fmaxf(ry1, g.y);             \
    float inter = fmaxf(iw, 0.0f) * ih;                         \
    float uni = (area_r + ag) - inter;                          \
    float iouv = __fdividef(inter, uni);                        \
    bool better = iouv > (BB);                                  \
    BB = better ? iouv : (BB);                                  \
    BJ = better ? (J)  : (BJ);                                  \
}

// merge: greater iou wins; exact tie -> smaller j (sentinel -1 never wins ties)
#define MERGE(OB, OJ) {                                         \
    bool take = ((OB) > best) ||                                \
        ((OB) == best && (unsigned)(OJ) < (unsigned)bj);        \
    best = take ? (OB) : best;                                  \
    bj   = take ? (OJ) : bj;                                    \
}

__global__ void __launch_bounds__(NT, 2) roitarget_fused(const float* __restrict__ rois,
                                                         const int* __restrict__ rb,
                                                         const float* __restrict__ gt,
                                                         const int* __restrict__ gb,
                                                         float* __restrict__ out) {
    __shared__ float  sgt[5 * N_GT];       // 20KB raw staged gt (coalesced)
    __shared__ float4 sbox[NGT_PAD];       // 18.4KB compacted x1,y1,x2+1,y2+1 (+pads)
    __shared__ float  sarea[NGT_PAD];      // 4.6KB areas (+pads)
    __shared__ float  slab[NGT_PAD];       // 4.6KB labels
    __shared__ float4 sroi[128];           // 2KB ROI coords by local index
    __shared__ int    sgcnt[32][9];        // per-chunk per-batch GT counts (padded)
    __shared__ int    sexcl[32][9];        // exclusive chunk prefix (padded)
    __shared__ int    stot[N_IMAGES];
    __shared__ int    soff[N_IMAGES + 1];  // PADDED batch offsets
    __shared__ int    snf[N_IMAGES];       // per-batch group count (padded len / 16)
    __shared__ int    swc[4][8];           // ROI counts per warp/batch
    __shared__ int    wbase[4][8];
    __shared__ int    sprovb[128], sprovr[128];
    __shared__ int    ssrc[128];           // sorted pos -> local ROI index
    __shared__ int    ssb[128];            // sorted pos -> batch

    const int tid  = threadIdx.x;
    const int w    = tid >> 5;
    const int lane = tid & 31;
    const unsigned lt = (1u << lane) - 1u;

    const int start = (blockIdx.x * N_ROIS) / NB;
    const int next  = ((blockIdx.x + 1) * N_ROIS) / NB;
    const int nroi  = next - start;        // 110 or 111

    // ---- coalesced GT staging + hoisted loads (overlap ballot phase) ----
#pragma unroll
    for (int k = 0; k < 10; k++) sgt[tid + k * NT] = gt[tid + k * NT];
    const int ja = tid, jb = tid + NT;     // chunks w and 16+w
    const int ba  = gb[ja];
    const int bb2 = gb[jb];
    int myb = -1;
    if (tid < nroi) {
        const int i = start + tid;
        myb = rb[i];
        sroi[tid] = make_float4(rois[5*i+0], rois[5*i+1], rois[5*i+2], rois[5*i+3]);
    }

    // ---- ballot counting: GT chunks (all warps, 2 chunks each) ----
    int ranka = 0, rankb = 0;
#pragma unroll
    for (int b = 0; b < N_IMAGES; b++) {
        unsigned ma = __ballot_sync(0xffffffffu, ba == b);
        if (ba == b) ranka = __popc(ma & lt);
        unsigned mb = __ballot_sync(0xffffffffu, bb2 == b);
        if (bb2 == b) rankb = __popc(mb & lt);
        if (lane == 0) { sgcnt[w][b] = __popc(ma); sgcnt[16 + w][b] = __popc(mb); }
    }
    // ---- ballot counting: ROIs (warps 0-3) ----
    if (w < 4) {
        int rank = 0;
#pragma unroll
        for (int b = 0; b < N_IMAGES; b++) {
            unsigned m = __ballot_sync(0xffffffffu, myb == b);
            if (myb == b) rank = __popc(m & lt);
            if (lane == 0) swc[w][b] = __popc(m);
        }
        if (tid < 128) { sprovb[tid] = myb; sprovr[tid] = rank; }
    }
    __syncthreads();                       // sync 1

    // ---- scans in parallel: warps 0-7 GT chunk-scan; warp 8 ROI bases ----
    if (w < N_IMAGES) {
        int v = sgcnt[lane][w];
        int incl = v;
#pragma unroll
        for (int d = 1; d < 32; d <<= 1) {
            int t = __shfl_up_sync(0xffffffffu, incl, d);
            if (lane >= d) incl += t;
        }
        sexcl[lane][w] = incl - v;
        if (lane == 31) stot[w] = incl;
    } else if (w == 8) {
        // single-warp exclusive scan over 32 (batch-major) cells: lane = b*4+w2
        int b2 = lane >> 2, w2 = lane & 3;
        int v = swc[w2][b2];
        int incl = v;
#pragma unroll
        for (int d = 1; d < 32; d <<= 1) {
            int t = __shfl_up_sync(0xffffffffu, incl, d);
            if (lane >= d) incl += t;
        }
        wbase[w2][b2] = incl - v;
    }
    __syncthreads();                       // sync 2

    // ---- per-warp redundant PADDED offsets (identical values; no barrier) ----
    if (lane == 0) {
        int o = 0;
#pragma unroll
        for (int b = 0; b < N_IMAGES; b++) {
            int plen = (stot[b] + 15) & ~15;
            soff[b] = o; snf[b] = plen >> 4; o += plen;
        }
        soff[N_IMAGES] = o;
    }
    __syncwarp();

    // ---- GT parse from staged smem (stride-5 LDS: conflict-free) + scatter ----
    {
        const float x1 = sgt[5*ja+0], y1 = sgt[5*ja+1];
        const float x2 = sgt[5*ja+2], y2 = sgt[5*ja+3], cls = sgt[5*ja+4];
        const int da = soff[ba] + sexcl[w][ba] + ranka;
        sbox[da]  = make_float4(x1, y1, x2 + 1.0f, y2 + 1.0f);
        sarea[da] = ((x2 - x1) + 1.0f) * ((y2 - y1) + 1.0f);
        slab[da]  = cls;

        const float u1 = sgt[5*jb+0], v1 = sgt[5*jb+1];
        const float u2 = sgt[5*jb+2], v2 = sgt[5*jb+3], cl2 = sgt[5*jb+4];
        const int db = soff[bb2] + sexcl[16 + w][bb2] + rankb;
        sbox[db]  = make_float4(u1, v1, u2 + 1.0f, v2 + 1.0f);
        sarea[db] = ((u2 - u1) + 1.0f) * ((v2 - v1) + 1.0f);
        slab[db]  = cl2;
    }
    // ---- write pad entries (never win: inter == 0, uni > 0) ----
    if (tid < 128) {
        const int b = tid >> 4, k = tid & 15;
        const int cnt  = stot[b];
        const int plen = (cnt + 15) & ~15;
        if (k < plen - cnt) {
            const int slot = soff[b] + cnt + k;
            sbox[slot]  = make_float4(3e9f, 0.0f, 1e9f, 1e9f);
            sarea[slot] = 1.0f;
            slab[slot]  = 0.0f;
        }
    }
    // ---- ROI scatter (warps 0-3) ----
    if (tid < nroi) {
        int pb = sprovb[tid];
        int dest = wbase[tid >> 5][pb] + sprovr[tid];
        ssrc[dest] = tid;                  // local index
        ssb[dest]  = pb;
    }
    __syncthreads();                       // sync 3

    // ---------------- Phase 3: 4 threads per ROI, interleaved quarters -----
    const int s = tid >> 2;                // ROI slot 0..127
    const int q = tid & 3;                 // quarter
    const bool valid = (s < nroi);
    const int loc = valid ? ssrc[s] : 0;
    const int b   = valid ? ssb[s]  : 0;

    const float4 rr = sroi[loc];
    const float rx1 = rr.x, ry1 = rr.y;
    const float rx2p = rr.z + 1.0f;
    const float ry2p = rr.w + 1.0f;
    const float ew = (rr.z - rx1) + 1.0f;
    const float eh = (rr.w - ry1) + 1.0f;
    const float area_r = ew * eh;

    const int j0 = soff[b];
    const int nfull = valid ? snf[b] : 0;  // 16-pair groups
    const int npair = nfull >> 1;          // 32-pair double groups

    float bb0 = 0.0f; int bj0 = -1;
    float bb1 = 0.0f; int bj1 = -1;
    float bb3 = 0.0f; int bj3 = -1;
    float bb4 = 0.0f; int bj4 = -1;

    int base = j0 + q;
    for (int t = 0; t < npair; t++, base += 32) {   // unroll x2: 8 steps/iter
        IOU_STEP(base + 0,  bb0, bj0);
        IOU_STEP(base + 4,  bb1, bj1);
        IOU_STEP(base + 8,  bb3, bj3);
        IOU_STEP(base + 12, bb4, bj4);
        IOU_STEP(base + 16, bb0, bj0);
        IOU_STEP(base + 20, bb1, bj1);
        IOU_STEP(base + 24, bb3, bj3);
        IOU_STEP(base + 28, bb4, bj4);
    }
    if (nfull & 1) {                                 // odd 16-group fixup
        IOU_STEP(base + 0,  bb0, bj0);
        IOU_STEP(base + 4,  bb1, bj1);
        IOU_STEP(base + 8,  bb3, bj3);
        IOU_STEP(base + 12, bb4, bj4);
    }

    // in-thread chain merge (ties -> smaller j)
    float best = bb0; int bj = bj0;
    MERGE(bb1, bj1);
    MERGE(bb3, bj3);
    MERGE(bb4, bj4);

    // cross-quarter butterfly merge (all lanes participate; idle slots carry -1)
#pragma unroll
    for (int d = 1; d <= 2; d <<= 1) {
        float ob = __shfl_xor_sync(0xffffffffu, best, d);
        int   oj = __shfl_xor_sync(0xffffffffu, bj, d);
        MERGE(ob, oj);
    }

    if (q == 0 && valid) {
        const bool fg = (bj >= 0) && (best >= 0.5f);
        const int ii = start + loc;

        float lbl = 0.0f, dx = 0.0f, dy = 0.0f, dw = 0.0f, dh = 0.0f, wgt = 0.0f;
        if (fg) {
            float4 g = sbox[bj];
            float gw  = g.z - g.x;             // (x2+1) - x1
            float gh  = g.w - g.y;
            float gcx = g.x + 0.5f * gw;
            float gcy = g.y + 0.5f * gh;
            float ecx = rx1 + 0.5f * ew;
            float ecy = ry1 + 0.5f * eh;
            dx = __fdividef(gcx - ecx, ew);    // 2^-21 rel err << 1e-3 tol
            dy = __fdividef(gcy - ecy, eh);
            dw = __logf(__fdividef(gw, ew));
            dh = __logf(__fdividef(gh, eh));
            lbl = slab[bj];
            wgt = 1.0f;
        }

        // Layout: labels[N] | deltas[N][4] | bbwgts[N][1]
        out[ii] = lbl;
        reinterpret_cast<float4*>(out + N_ROIS)[ii] = make_float4(dx, dy, dw, dh);
        out[N_ROIS * 5 + ii] = wgt;
    }
}

extern "C" void kernel_launch(void* const* d_in, const int* in_sizes, int n_in,
                              void* d_out, int out_size) {
    const float* rois = (const float*)d_in[0];
    const int*   rb   = (const int*)d_in[1];
    const float* gt   = (const float*)d_in[2];
    const int*   gb   = (const int*)d_in[3];
    float* out = (float*)d_out;

    roitarget_fused<<<NB, NT>>>(rois, rb, gt, gb, out);
}

// round 15
// speedup vs baseline: 1.2216x; 1.1946x over previous
#include <cuda_runtime.h>
#include <cuda_bf16.h>
#include <cstdint>

#define N_ROIS   32768
#define N_GT     1024
#define N_IMAGES 8
#define NT       512
#define NB       148                 // 1 block per SM, single wave
#define NGT_PAD  1152
#define MAXROI   224                 // >= max nroi (222)

// shared-GT dual-ROI step: one LDS feeds both ROIs of the pair
#define IOU2_STEP(J, BA, JA, BP, JP) {                          \
    float4 g  = sbox[J];                                        \
    float ag  = sarea[J];                                       \
    /* ROI A */                                                 \
    float iwa = fminf(ax2p, g.z) - fmaxf(ax1, g.x);             \
    float iha = fminf(ay2p, g.w) - fmaxf(ay1, g.y);             \
    float ina = fmaxf(iwa, 0.0f) * iha;                         \
    float una = (area_a + ag) - ina;                            \
    float iva = __fdividef(ina, una);                           \
    bool ba_ = iva > (BA);                                      \
    BA = ba_ ? iva : (BA);                                      \
    JA = ba_ ? (J) : (JA);                                      \
    /* ROI B */                                                 \
    float iwb = fminf(bx2p, g.z) - fmaxf(bx1, g.x);             \
    float ihb = fminf(by2p, g.w) - fmaxf(by1, g.y);             \
    float inb = fmaxf(iwb, 0.0f) * ihb;                         \
    float unb = (area_b + ag) - inb;                            \
    float ivb = __fdividef(inb, unb);                           \
    bool bb_ = ivb > (BP);                                      \
    BP = bb_ ? ivb : (BP);                                      \
    JP = bb_ ? (J) : (JP);                                      \
}

#define MERGEV(BST, BJ, OB, OJ) {                               \
    bool take = ((OB) > (BST)) ||                               \
        ((OB) == (BST) && (unsigned)(OJ) < (unsigned)(BJ));     \
    BST = take ? (OB) : (BST);                                  \
    BJ  = take ? (OJ) : (BJ);                                   \
}

__global__ void __launch_bounds__(NT, 1) roitarget_fused(const float* __restrict__ rois,
                                                         const int* __restrict__ rb,
                                                         const float* __restrict__ gt,
                                                         const int* __restrict__ gb,
                                                         float* __restrict__ out) {
    __shared__ float  sgt[5 * N_GT];       // 20KB raw staged gt (coalesced)
    __shared__ float4 sbox[NGT_PAD];       // 18.4KB compacted boxes (+pads)
    __shared__ float  sarea[NGT_PAD];      // 4.6KB areas (+pads)
    __shared__ float  slab[NGT_PAD];       // 4.6KB labels
    __shared__ float4 sroi[MAXROI];        // 3.5KB ROI coords by local index
    __shared__ int    sgcnt[32][9];        // per-chunk per-batch GT counts
    __shared__ int    sexcl[32][9];        // exclusive chunk prefix
    __shared__ int    stot[N_IMAGES];
    __shared__ int    soff[N_IMAGES + 1];  // padded GT batch offsets
    __shared__ int    snf[N_IMAGES];       // padded len / 16
    __shared__ int    swc[7][8];           // ROI counts per warp/batch
    __shared__ int    wbase[7][8];
    __shared__ int    rstart[N_IMAGES + 1];// ROI bucket starts
    __shared__ int    pairoff[N_IMAGES + 1];// pair-slot offsets
    __shared__ int    sprovb[MAXROI], sprovr[MAXROI];
    __shared__ int    ssrc[MAXROI];        // sorted pos -> local ROI index

    const int tid  = threadIdx.x;
    const int w    = tid >> 5;
    const int lane = tid & 31;
    const unsigned lt = (1u << lane) - 1u;

    const int start = (blockIdx.x * N_ROIS) / NB;
    const int next  = ((blockIdx.x + 1) * N_ROIS) / NB;
    const int nroi  = next - start;        // 221 or 222

    // ---- coalesced GT staging + hoisted loads ----
#pragma unroll
    for (int k = 0; k < 10; k++) sgt[tid + k * NT] = gt[tid + k * NT];
    const int ja = tid, jb = tid + NT;     // chunks w and 16+w
    const int ba  = gb[ja];
    const int bb2 = gb[jb];
    int myb = -1;
    if (tid < nroi) {
        const int i = start + tid;
        myb = rb[i];
        sroi[tid] = make_float4(rois[5*i+0], rois[5*i+1], rois[5*i+2], rois[5*i+3]);
    }

    // ---- ballot counting: GT chunks (all warps, 2 chunks each) ----
    int ranka = 0, rankb = 0;
#pragma unroll
    for (int b = 0; b < N_IMAGES; b++) {
        unsigned ma = __ballot_sync(0xffffffffu, ba == b);
        if (ba == b) ranka = __popc(ma & lt);
        unsigned mb = __ballot_sync(0xffffffffu, bb2 == b);
        if (bb2 == b) rankb = __popc(mb & lt);
        if (lane == 0) { sgcnt[w][b] = __popc(ma); sgcnt[16 + w][b] = __popc(mb); }
    }
    // ---- ballot counting: ROIs (warps 0-6 cover 224 slots) ----
    if (w < 7) {
        int rank = 0;
#pragma unroll
        for (int b = 0; b < N_IMAGES; b++) {
            unsigned m = __ballot_sync(0xffffffffu, myb == b);
            if (myb == b) rank = __popc(m & lt);
            if (lane == 0) swc[w][b] = __popc(m);
        }
        sprovb[tid] = myb;
        sprovr[tid] = rank;
    }
    __syncthreads();                       // sync 1

    // ---- scans: warps 0-7 GT chunk-scan; warps 8-9 ROI bases (serial) ----
    if (w < N_IMAGES) {
        int v = sgcnt[lane][w];
        int incl = v;
#pragma unroll
        for (int d = 1; d < 32; d <<= 1) {
            int t = __shfl_up_sync(0xffffffffu, incl, d);
            if (lane >= d) incl += t;
        }
        sexcl[lane][w] = incl - v;
        if (lane == 31) stot[w] = incl;
    } else if (w == 8 || w == 9) {
        int e = (w - 8) * 32 + lane;       // 0..63
        if (e < 56) {
            int ww = e % 7, b2 = e / 7;
            int o = 0;
            for (int b3 = 0; b3 < b2; b3++)
#pragma unroll
                for (int w2 = 0; w2 < 7; w2++) o += swc[w2][b3];
            for (int w2 = 0; w2 < ww; w2++) o += swc[w2][b2];
            wbase[ww][b2] = o;
        }
    }
    __syncthreads();                       // sync 2

    // ---- per-warp redundant offsets (identical values; no barrier) ----
    if (lane == 0) {
        int o = 0;
#pragma unroll
        for (int b = 0; b < N_IMAGES; b++) {
            int plen = (stot[b] + 15) & ~15;
            soff[b] = o; snf[b] = plen >> 4; o += plen;
        }
        soff[N_IMAGES] = o;
        int po = 0;
#pragma unroll
        for (int b = 0; b < N_IMAGES; b++) {
            rstart[b] = wbase[0][b];
            pairoff[b] = po;
        }
        rstart[N_IMAGES] = nroi;
#pragma unroll
        for (int b = 0; b < N_IMAGES; b++) {
            int nb2 = (b < 7 ? wbase[0][b + 1] : nroi) - wbase[0][b];
            pairoff[b] = po;
            po += (nb2 + 1) >> 1;
        }
        pairoff[N_IMAGES] = po;
    }
    __syncwarp();

    // ---- GT parse + scatter ----
    {
        const float x1 = sgt[5*ja+0], y1 = sgt[5*ja+1];
        const float x2 = sgt[5*ja+2], y2 = sgt[5*ja+3], cls = sgt[5*ja+4];
        const int da = soff[ba] + sexcl[w][ba] + ranka;
        sbox[da]  = make_float4(x1, y1, x2 + 1.0f, y2 + 1.0f);
        sarea[da] = ((x2 - x1) + 1.0f) * ((y2 - y1) + 1.0f);
        slab[da]  = cls;

        const float u1 = sgt[5*jb+0], v1 = sgt[5*jb+1];
        const float u2 = sgt[5*jb+2], v2 = sgt[5*jb+3], cl2 = sgt[5*jb+4];
        const int db = soff[bb2] + sexcl[16 + w][bb2] + rankb;
        sbox[db]  = make_float4(u1, v1, u2 + 1.0f, v2 + 1.0f);
        sarea[db] = ((u2 - u1) + 1.0f) * ((v2 - v1) + 1.0f);
        slab[db]  = cl2;
    }
    // ---- pad entries (never win: inter == 0, uni > 0) ----
    if (tid < 128) {
        const int b = tid >> 4, k = tid & 15;
        const int cnt  = stot[b];
        const int plen = (cnt + 15) & ~15;
        if (k < plen - cnt) {
            const int slot = soff[b] + cnt + k;
            sbox[slot]  = make_float4(3e9f, 0.0f, 1e9f, 1e9f);
            sarea[slot] = 1.0f;
            slab[slot]  = 0.0f;
        }
    }
    // ---- ROI scatter ----
    if (tid < nroi) {
        int pb = sprovb[tid];
        int dest = wbase[w][pb] + sprovr[tid];
        ssrc[dest] = tid;
    }
    __syncthreads();                       // sync 3

    // ---------------- Phase 3: thread-quad per ROI PAIR --------------------
    const int s = tid >> 2;                // pair slot 0..127
    const int q = tid & 3;                 // quarter
    const int npairs = pairoff[N_IMAGES];
    const bool valid = (s < npairs);

    int b = 0;
#pragma unroll
    for (int k = 1; k < N_IMAGES; k++) b += (s >= pairoff[k]);
    const int k2   = s - pairoff[b];
    const int rcnt = rstart[b + 1] - rstart[b];
    const int pa   = valid ? (rstart[b] + 2 * k2) : 0;
    const bool dual = valid && (2 * k2 + 1 < rcnt);
    const int pbx  = pa + (dual ? 1 : 0);
    const int loca = ssrc[pa];
    const int locb = ssrc[pbx];

    const float4 ra = sroi[loca];
    const float ax1 = ra.x, ay1 = ra.y;
    const float ax2p = ra.z + 1.0f, ay2p = ra.w + 1.0f;
    const float aew = (ra.z - ax1) + 1.0f, aeh = (ra.w - ay1) + 1.0f;
    const float area_a = aew * aeh;

    const float4 rbv = sroi[locb];
    const float bx1 = rbv.x, by1 = rbv.y;
    const float bx2p = rbv.z + 1.0f, by2p = rbv.w + 1.0f;
    const float bew = (rbv.z - bx1) + 1.0f, beh = (rbv.w - by1) + 1.0f;
    const float area_b = bew * beh;

    const int j0 = soff[b];
    const int nfull = valid ? snf[b] : 0;

    float ba0 = 0.0f; int ja0 = -1;        // ROI A chains
    float ba1 = 0.0f; int ja1 = -1;
    float bp0 = 0.0f; int jp0 = -1;        // ROI B chains
    float bp1 = 0.0f; int jp1 = -1;

    int base = j0 + q;
    for (int t = 0; t < nfull; t++, base += 16) {
        IOU2_STEP(base + 0,  ba0, ja0, bp0, jp0);
        IOU2_STEP(base + 4,  ba1, ja1, bp1, jp1);
        IOU2_STEP(base + 8,  ba0, ja0, bp0, jp0);
        IOU2_STEP(base + 12, ba1, ja1, bp1, jp1);
    }

    // in-thread chain merges (ties -> smaller j)
    float bestA = ba0; int bjA = ja0;
    MERGEV(bestA, bjA, ba1, ja1);
    float bestB = bp0; int bjB = jp0;
    MERGEV(bestB, bjB, bp1, jp1);

    // cross-quarter butterfly merges (all lanes participate)
#pragma unroll
    for (int d = 1; d <= 2; d <<= 1) {
        float oa = __shfl_xor_sync(0xffffffffu, bestA, d);
        int   na = __shfl_xor_sync(0xffffffffu, bjA, d);
        MERGEV(bestA, bjA, oa, na);
        float ob = __shfl_xor_sync(0xffffffffu, bestB, d);
        int   nb2 = __shfl_xor_sync(0xffffffffu, bjB, d);
        MERGEV(bestB, bjB, ob, nb2);
    }

    // epilogue: q==0 stores ROI A; q==1 stores ROI B (if distinct)
    if (valid && (q == 0 || (q == 1 && dual))) {
        const bool isA = (q == 0);
        const float best = isA ? bestA : bestB;
        const int   bj   = isA ? bjA   : bjB;
        const int   loc  = isA ? loca  : locb;
        const float rx1v = isA ? ax1 : bx1;
        const float ry1v = isA ? ay1 : by1;
        const float ewv  = isA ? aew : bew;
        const float ehv  = isA ? aeh : beh;

        const bool fg = (bj >= 0) && (best >= 0.5f);
        const int ii = start + loc;

        float lbl = 0.0f, dx = 0.0f, dy = 0.0f, dw = 0.0f, dh = 0.0f, wgt = 0.0f;
        if (fg) {
            float4 g = sbox[bj];
            float gw  = g.z - g.x;             // (x2+1) - x1
            float gh  = g.w - g.y;
            float gcx = g.x + 0.5f * gw;
            float gcy = g.y + 0.5f * gh;
            float ecx = rx1v + 0.5f * ewv;
            float ecy = ry1v + 0.5f * ehv;
            dx = __fdividef(gcx - ecx, ewv);
            dy = __fdividef(gcy - ecy, ehv);
            dw = __logf(__fdividef(gw, ewv));
            dh = __logf(__fdividef(gh, ehv));
            lbl = slab[bj];
            wgt = 1.0f;
        }

        // Layout: labels[N] | deltas[N][4] | bbwgts[N][1]
        out[ii] = lbl;
        reinterpret_cast<float4*>(out + N_ROIS)[ii] = make_float4(dx, dy, dw, dh);
        out[N_ROIS * 5 + ii] = wgt;
    }
}

extern "C" void kernel_launch(void* const* d_in, const int* in_sizes, int n_in,
                              void* d_out, int out_size) {
    const float* rois = (const float*)d_in[0];
    const int*   rb   = (const int*)d_in[1];
    const float* gt   = (const float*)d_in[2];
    const int*   gb   = (const int*)d_in[3];
    float* out = (float*)d_out;

    roitarget_fused<<<NB, NT>>>(rois, rb, gt, gb, out);
}